// round 5
// baseline (speedup 1.0000x reference)
#include <cuda_runtime.h>

#define BB 4
#define HH 64
#define WW 64
#define BANDS 128
#define CC 32
#define NPIX (BB*HH*WW)        // 16384
#define ALPHA 0.3f

// Scratch: intermediates for the two conv chains
__device__ float g_h1g[NPIX*CC];
__device__ float g_h1b[NPIX*CC];
__device__ float g_gamma[NPIX*CC];
__device__ float g_beta[NPIX*CC];

// blockIdx.y in [0,8): branch = y>>2 (0=gamma,1=beta), quarter = y&3 (8 out-channels)
// stage 0: psi -> h1{g,b};  stage 1: h1{g,b} -> {gamma,beta}
__global__ __launch_bounds__(128) void conv_quarter_kernel(
    int stage,
    const float* __restrict__ psi,
    const float* __restrict__ wA, const float* __restrict__ bA,
    const float* __restrict__ wB, const float* __restrict__ bB)
{
    // weights for this quarter: [9*CC input rows][2 float4 of out-channels] = 9 KB
    __shared__ float4 sW[9*CC*2];
    __shared__ float  sBias[8];

    const int yb      = blockIdx.y;
    const int branch  = yb >> 2;
    const int quarter = yb & 3;

    const float* in;
    float* out;
    if (stage == 0) {
        in  = psi;
        out = branch ? g_h1b : g_h1g;
    } else {
        in  = branch ? g_h1b : g_h1g;
        out = branch ? g_beta : g_gamma;
    }
    const float* wsrc = branch ? wB : wA;
    const float* bsrc = branch ? bB : bA;

    // Stage quarter-slice of weights: for each of 9*32 (kpos,ci) rows,
    // two float4 covering out-channels [quarter*8, quarter*8+8)
    #pragma unroll
    for (int i = threadIdx.x; i < 9*CC*2; i += 128) {
        const int kci  = i >> 1;
        const int pair = i & 1;
        sW[i] = *(const float4*)(wsrc + kci*CC + quarter*8 + pair*4);
    }
    if (threadIdx.x < 8) sBias[threadIdx.x] = bsrc[quarter*8 + threadIdx.x];
    __syncthreads();

    const unsigned p = blockIdx.x * 128u + threadIdx.x;   // pixel id
    const int b = p >> 12;
    const int y = (p >> 6) & 63;
    const int x = p & 63;

    float acc[8];
    #pragma unroll
    for (int co = 0; co < 8; co++) acc[co] = sBias[co];

    #pragma unroll
    for (int ky = 0; ky < 3; ky++) {
        const int iy = y + ky - 1;
        if (iy < 0 || iy >= HH) continue;
        #pragma unroll
        for (int kx = 0; kx < 3; kx++) {
            const int ix = x + kx - 1;
            if (ix < 0 || ix >= WW) continue;
            const float4* ip = (const float4*)(in + (((b*HH) + iy)*WW + ix)*CC);
            const int kbase = (ky*3 + kx) * CC;   // row offset in (kpos,ci) space
            #pragma unroll
            for (int j = 0; j < 8; j++) {         // 8 float4 = 32 input channels
                const float4 iv = ip[j];
                #pragma unroll
                for (int r = 0; r < 4; r++) {
                    const float v = (r == 0) ? iv.x : (r == 1) ? iv.y : (r == 2) ? iv.z : iv.w;
                    const int row = (kbase + 4*j + r) * 2;
                    const float4 w0 = sW[row + 0];
                    const float4 w1 = sW[row + 1];
                    acc[0] = fmaf(v, w0.x, acc[0]);
                    acc[1] = fmaf(v, w0.y, acc[1]);
                    acc[2] = fmaf(v, w0.z, acc[2]);
                    acc[3] = fmaf(v, w0.w, acc[3]);
                    acc[4] = fmaf(v, w1.x, acc[4]);
                    acc[5] = fmaf(v, w1.y, acc[5]);
                    acc[6] = fmaf(v, w1.z, acc[6]);
                    acc[7] = fmaf(v, w1.w, acc[7]);
                }
            }
        }
    }

    float4* op = (float4*)(out + p*CC + quarter*8);
    #pragma unroll
    for (int h = 0; h < 2; h++) {
        float a0 = acc[4*h+0], a1 = acc[4*h+1], a2 = acc[4*h+2], a3 = acc[4*h+3];
        float4 rr;
        rr.x = a0 > 0.f ? a0 : ALPHA*a0;
        rr.y = a1 > 0.f ? a1 : ALPHA*a1;
        rr.z = a2 > 0.f ? a2 : ALPHA*a2;
        rr.w = a3 > 0.f ? a3 : ALPHA*a3;
        op[h] = rr;
    }
}

// out[b,h,w,band,c] = x * gamma[b,h,w,c] + beta[b,h,w,c]
__global__ __launch_bounds__(256) void film_kernel(
    const float4* __restrict__ x, float4* __restrict__ out)
{
    const unsigned long long i = (unsigned long long)blockIdx.x * 256u + threadIdx.x;
    const unsigned c4  = (unsigned)(i & 7u);
    const unsigned pix = (unsigned)(i >> 10);
    const unsigned gidx = pix*8u + c4;

    const float4 xv = x[i];
    const float4 gv = __ldg(((const float4*)g_gamma) + gidx);
    const float4 bv = __ldg(((const float4*)g_beta)  + gidx);

    float4 r;
    r.x = fmaf(xv.x, gv.x, bv.x);
    r.y = fmaf(xv.y, gv.y, bv.y);
    r.z = fmaf(xv.z, gv.z, bv.z);
    r.w = fmaf(xv.w, gv.w, bv.w);
    out[i] = r;
}

extern "C" void kernel_launch(void* const* d_in, const int* in_sizes, int n_in,
                              void* d_out, int out_size)
{
    const float* x   = (const float*)d_in[0];
    const float* psi = (const float*)d_in[1];
    const float* gw1 = (const float*)d_in[2];
    const float* gb1 = (const float*)d_in[3];
    const float* gw2 = (const float*)d_in[4];
    const float* gb2 = (const float*)d_in[5];
    const float* bw1 = (const float*)d_in[6];
    const float* bb1 = (const float*)d_in[7];
    const float* bw2 = (const float*)d_in[8];
    const float* bb2 = (const float*)d_in[9];

    dim3 gridc(NPIX/128, 8);
    conv_quarter_kernel<<<gridc, 128>>>(0, psi, gw1, gb1, bw1, bb1);
    conv_quarter_kernel<<<gridc, 128>>>(1, psi, gw2, gb2, bw2, bb2);

    const int n4 = NPIX * BANDS * (CC/4);     // 16,777,216 float4
    film_kernel<<<n4/256, 256>>>((const float4*)x, (float4*)d_out);
}

// round 12
// speedup vs baseline: 1.2824x; 1.2824x over previous
#include <cuda_runtime.h>

#define BB 4
#define HH 64
#define WW 64
#define BANDS 128
#define CC 32
#define NPIX (BB*HH*WW)        // 16384
#define ALPHA 0.3f

#define TW 8                   // tile width (x)
#define TH 8                   // tile height (y)
#define PW 10                  // patch width  (halo)
#define PH 10                  // patch height
#define PPIX (PW*PH)           // 100
#define PPLANE 101             // padded plane stride (conflict-free)
#define NW_FLOATS (9*CC*CC)    // 9216 weight floats
#define SMEM_FLOATS (NW_FLOATS + CC*PPLANE + CC)   // 9216 + 3232 + 32 = 12480
#define SMEM_BYTES (SMEM_FLOATS*4)                 // 49920

// Scratch: intermediates for the two conv chains
__device__ float g_h1g[NPIX*CC];
__device__ float g_h1b[NPIX*CC];
__device__ float g_gamma[NPIX*CC];
__device__ float g_beta[NPIX*CC];

// blockIdx.x: tile id (256 per branch), blockIdx.y: branch (0=gamma, 1=beta)
// stage 0: psi -> h1{g,b};  stage 1: h1{g,b} -> {gamma,beta}
__global__ __launch_bounds__(TW*TH, 4) void conv_tile_kernel(
    int stage,
    const float* __restrict__ psi,
    const float* __restrict__ wA, const float* __restrict__ bA,
    const float* __restrict__ wB, const float* __restrict__ bB)
{
    extern __shared__ float smem[];
    float* sW = smem;                       // [9*CC][CC], same layout as HWIO gmem
    float* sP = smem + NW_FLOATS;           // [CC][PPLANE] channel-major patch
    float* sB = sP + CC*PPLANE;             // [CC]

    const int branch = blockIdx.y;
    const float* in;
    float* out;
    if (stage == 0) {
        in  = psi;
        out = branch ? g_h1b : g_h1g;
    } else {
        in  = branch ? g_h1b : g_h1g;
        out = branch ? g_beta : g_gamma;
    }
    const float* wsrc = branch ? wB : wA;
    const float* bsrc = branch ? bB : bA;

    const int tid = threadIdx.x;

    // ---- stage weights (straight copy, coalesced float4) ----
    {
        const float4* w4 = (const float4*)wsrc;
        float4* s4 = (float4*)sW;
        #pragma unroll
        for (int i = tid; i < NW_FLOATS/4; i += TW*TH) s4[i] = w4[i];
        if (tid < CC) sB[tid] = bsrc[tid];
    }

    // ---- tile coords ----
    const int bx = blockIdx.x;              // 0..255
    const int b  = bx >> 6;                 // batch
    const int t  = bx & 63;
    const int y0 = (t >> 3) * TH;
    const int x0 = (t & 7) * TW;

    // ---- stage input patch: coalesced gmem read, channel-major smem write ----
    // idx: ci fastest (coalesced), pixel-linear next
    for (int idx = tid; idx < PPIX*CC; idx += TW*TH) {
        const int ci = idx & 31;
        const int pl = idx >> 5;            // 0..99
        const int py = pl / PW;
        const int px = pl - py*PW;
        const int gy = y0 - 1 + py;
        const int gx = x0 - 1 + px;
        float v = 0.f;
        if (gy >= 0 && gy < HH && gx >= 0 && gx < WW)
            v = in[(((b*HH) + gy)*WW + gx)*CC + ci];
        sP[ci*PPLANE + pl] = v;
    }
    __syncthreads();

    // ---- compute: each thread = one pixel, all 32 output channels ----
    const int tx = tid & 7;
    const int ty = tid >> 3;

    float acc[CC];
    #pragma unroll
    for (int co = 0; co < CC; co++) acc[co] = sB[co];

    #pragma unroll
    for (int ky = 0; ky < 3; ky++) {
        #pragma unroll
        for (int kx = 0; kx < 3; kx++) {
            const int off = (ty + ky)*PW + (tx + kx);      // patch pixel
            const int kb  = (ky*3 + kx) * CC;              // weight row base
            #pragma unroll 4
            for (int ci = 0; ci < CC; ci++) {
                const float v = sP[ci*PPLANE + off];       // broadcast LDS
                const float4* wr = (const float4*)&sW[(kb + ci)*CC];
                #pragma unroll
                for (int j = 0; j < 8; j++) {
                    const float4 wv = wr[j];
                    acc[4*j+0] = fmaf(v, wv.x, acc[4*j+0]);
                    acc[4*j+1] = fmaf(v, wv.y, acc[4*j+1]);
                    acc[4*j+2] = fmaf(v, wv.z, acc[4*j+2]);
                    acc[4*j+3] = fmaf(v, wv.w, acc[4*j+3]);
                }
            }
        }
    }

    // ---- leaky relu + store (coalesced-ish float4; 8 per thread) ----
    const int p = ((b*HH) + (y0 + ty))*WW + (x0 + tx);
    float4* op = (float4*)(out + p*CC);
    #pragma unroll
    for (int j = 0; j < 8; j++) {
        float a0 = acc[4*j+0], a1 = acc[4*j+1], a2 = acc[4*j+2], a3 = acc[4*j+3];
        float4 r;
        r.x = a0 > 0.f ? a0 : ALPHA*a0;
        r.y = a1 > 0.f ? a1 : ALPHA*a1;
        r.z = a2 > 0.f ? a2 : ALPHA*a2;
        r.w = a3 > 0.f ? a3 : ALPHA*a3;
        op[j] = r;
    }
}

// out[b,h,w,band,c] = x * gamma[b,h,w,c] + beta[b,h,w,c]
__global__ __launch_bounds__(256) void film_kernel(
    const float4* __restrict__ x, float4* __restrict__ out)
{
    const unsigned long long i = (unsigned long long)blockIdx.x * 256u + threadIdx.x;
    const unsigned c4  = (unsigned)(i & 7u);
    const unsigned pix = (unsigned)(i >> 10);
    const unsigned gidx = pix*8u + c4;

    const float4 xv = x[i];
    const float4 gv = __ldg(((const float4*)g_gamma) + gidx);
    const float4 bv = __ldg(((const float4*)g_beta)  + gidx);

    float4 r;
    r.x = fmaf(xv.x, gv.x, bv.x);
    r.y = fmaf(xv.y, gv.y, bv.y);
    r.z = fmaf(xv.z, gv.z, bv.z);
    r.w = fmaf(xv.w, gv.w, bv.w);
    out[i] = r;
}

extern "C" void kernel_launch(void* const* d_in, const int* in_sizes, int n_in,
                              void* d_out, int out_size)
{
    const float* x   = (const float*)d_in[0];
    const float* psi = (const float*)d_in[1];
    const float* gw1 = (const float*)d_in[2];
    const float* gb1 = (const float*)d_in[3];
    const float* gw2 = (const float*)d_in[4];
    const float* gb2 = (const float*)d_in[5];
    const float* bw1 = (const float*)d_in[6];
    const float* bb1 = (const float*)d_in[7];
    const float* bw2 = (const float*)d_in[8];
    const float* bb2 = (const float*)d_in[9];

    cudaFuncSetAttribute(conv_tile_kernel,
                         cudaFuncAttributeMaxDynamicSharedMemorySize, SMEM_BYTES);

    dim3 gridc(256, 2);
    conv_tile_kernel<<<gridc, TW*TH, SMEM_BYTES>>>(0, psi, gw1, gb1, bw1, bb1);
    conv_tile_kernel<<<gridc, TW*TH, SMEM_BYTES>>>(1, psi, gw2, gb2, bw2, bb2);

    const int n4 = NPIX * BANDS * (CC/4);     // 16,777,216 float4
    film_kernel<<<n4/256, 256>>>((const float4*)x, (float4*)d_out);
}

// round 17
// speedup vs baseline: 1.3126x; 1.0235x over previous
#include <cuda_runtime.h>

#define BB 4
#define HH 64
#define WW 64
#define BANDS 128
#define CC 32
#define NPIX (BB*HH*WW)        // 16384
#define ALPHA 0.3f

#define TW 8                   // tile width (x)
#define TH 8                   // tile height (y)
#define NT 128                 // threads per block (2 per pixel)
#define PW 10                  // patch width  (halo)
#define PH 10                  // patch height
#define PPIX (PW*PH)           // 100
#define PPLANE 101             // padded plane stride (conflict-free)
#define NW_FLOATS (9*CC*CC)    // 9216 weight floats
#define SMEM_FLOATS (NW_FLOATS + CC*PPLANE + CC)   // 12480
#define SMEM_BYTES (SMEM_FLOATS*4)                 // 49920

// Scratch: intermediates for the two conv chains
__device__ float g_h1g[NPIX*CC];
__device__ float g_h1b[NPIX*CC];
__device__ float g_gamma[NPIX*CC];
__device__ float g_beta[NPIX*CC];

// blockIdx.x: tile id (256 per branch), blockIdx.y: branch (0=gamma, 1=beta)
// 128 threads: threads 0-63 pixel half 0 (out ch 0-15), 64-127 half 1 (ch 16-31)
__global__ __launch_bounds__(NT, 4) void conv_tile_kernel(
    int stage,
    const float* __restrict__ psi,
    const float* __restrict__ wA, const float* __restrict__ bA,
    const float* __restrict__ wB, const float* __restrict__ bB)
{
    extern __shared__ float smem[];
    float* sW = smem;                       // [9*CC][CC], HWIO layout
    float* sP = smem + NW_FLOATS;           // [CC][PPLANE] channel-major patch
    float* sB = sP + CC*PPLANE;             // [CC]

    const int branch = blockIdx.y;
    const float* in;
    float* out;
    if (stage == 0) {
        in  = psi;
        out = branch ? g_h1b : g_h1g;
    } else {
        in  = branch ? g_h1b : g_h1g;
        out = branch ? g_beta : g_gamma;
    }
    const float* wsrc = branch ? wB : wA;
    const float* bsrc = branch ? bB : bA;

    const int tid = threadIdx.x;

    // ---- stage weights (coalesced float4 copy) ----
    {
        const float4* w4 = (const float4*)wsrc;
        float4* s4 = (float4*)sW;
        #pragma unroll
        for (int i = tid; i < NW_FLOATS/4; i += NT) s4[i] = w4[i];
        if (tid < CC) sB[tid] = bsrc[tid];
    }

    // ---- tile coords ----
    const int bx = blockIdx.x;              // 0..255
    const int b  = bx >> 6;                 // batch
    const int t  = bx & 63;
    const int y0 = (t >> 3) * TH;
    const int x0 = (t & 7) * TW;

    // ---- stage input patch: coalesced gmem read, channel-major smem write ----
    for (int idx = tid; idx < PPIX*CC; idx += NT) {
        const int ci = idx & 31;
        const int pl = idx >> 5;            // 0..99
        const int py = pl / PW;
        const int px = pl - py*PW;
        const int gy = y0 - 1 + py;
        const int gx = x0 - 1 + px;
        float v = 0.f;
        if (gy >= 0 && gy < HH && gx >= 0 && gx < WW)
            v = in[(((b*HH) + gy)*WW + gx)*CC + ci];
        sP[ci*PPLANE + pl] = v;
    }
    __syncthreads();

    // ---- compute: 2 threads per pixel, 16 output channels each ----
    const int pix  = tid & 63;              // pixel within tile
    const int half = tid >> 6;              // 0 or 1
    const int tx = pix & 7;
    const int ty = pix >> 3;
    const int cbase = half * 4;             // float4 offset into weight row

    float acc[16];
    #pragma unroll
    for (int k = 0; k < 16; k++) acc[k] = sB[half*16 + k];

    #pragma unroll
    for (int ky = 0; ky < 3; ky++) {
        #pragma unroll
        for (int kx = 0; kx < 3; kx++) {
            const int off = (ty + ky)*PW + (tx + kx);      // patch pixel
            const int kb  = (ky*3 + kx) * CC;              // weight row base
            #pragma unroll 4
            for (int ci = 0; ci < CC; ci++) {
                const float v = sP[ci*PPLANE + off];       // broadcast LDS
                const float4* wr = (const float4*)&sW[(kb + ci)*CC] + cbase;
                #pragma unroll
                for (int j = 0; j < 4; j++) {
                    const float4 wv = wr[j];
                    acc[4*j+0] = fmaf(v, wv.x, acc[4*j+0]);
                    acc[4*j+1] = fmaf(v, wv.y, acc[4*j+1]);
                    acc[4*j+2] = fmaf(v, wv.z, acc[4*j+2]);
                    acc[4*j+3] = fmaf(v, wv.w, acc[4*j+3]);
                }
            }
        }
    }

    // ---- leaky relu + store (4 float4 per thread) ----
    const int p = ((b*HH) + (y0 + ty))*WW + (x0 + tx);
    float4* op = (float4*)(out + p*CC + half*16);
    #pragma unroll
    for (int j = 0; j < 4; j++) {
        float a0 = acc[4*j+0], a1 = acc[4*j+1], a2 = acc[4*j+2], a3 = acc[4*j+3];
        float4 r;
        r.x = a0 > 0.f ? a0 : ALPHA*a0;
        r.y = a1 > 0.f ? a1 : ALPHA*a1;
        r.z = a2 > 0.f ? a2 : ALPHA*a2;
        r.w = a3 > 0.f ? a3 : ALPHA*a3;
        op[j] = r;
    }
}

// out[b,h,w,band,c] = x * gamma[b,h,w,c] + beta[b,h,w,c]
__global__ __launch_bounds__(256) void film_kernel(
    const float4* __restrict__ x, float4* __restrict__ out)
{
    const unsigned long long i = (unsigned long long)blockIdx.x * 256u + threadIdx.x;
    const unsigned c4  = (unsigned)(i & 7u);
    const unsigned pix = (unsigned)(i >> 10);
    const unsigned gidx = pix*8u + c4;

    const float4 xv = x[i];
    const float4 gv = __ldg(((const float4*)g_gamma) + gidx);
    const float4 bv = __ldg(((const float4*)g_beta)  + gidx);

    float4 r;
    r.x = fmaf(xv.x, gv.x, bv.x);
    r.y = fmaf(xv.y, gv.y, bv.y);
    r.z = fmaf(xv.z, gv.z, bv.z);
    r.w = fmaf(xv.w, gv.w, bv.w);
    out[i] = r;
}

extern "C" void kernel_launch(void* const* d_in, const int* in_sizes, int n_in,
                              void* d_out, int out_size)
{
    const float* x   = (const float*)d_in[0];
    const float* psi = (const float*)d_in[1];
    const float* gw1 = (const float*)d_in[2];
    const float* gb1 = (const float*)d_in[3];
    const float* gw2 = (const float*)d_in[4];
    const float* gb2 = (const float*)d_in[5];
    const float* bw1 = (const float*)d_in[6];
    const float* bb1 = (const float*)d_in[7];
    const float* bw2 = (const float*)d_in[8];
    const float* bb2 = (const float*)d_in[9];

    cudaFuncSetAttribute(conv_tile_kernel,
                         cudaFuncAttributeMaxDynamicSharedMemorySize, SMEM_BYTES);

    dim3 gridc(256, 2);
    conv_tile_kernel<<<gridc, NT, SMEM_BYTES>>>(0, psi, gw1, gb1, bw1, bb1);
    conv_tile_kernel<<<gridc, NT, SMEM_BYTES>>>(1, psi, gw2, gb2, bw2, bb2);

    const int n4 = NPIX * BANDS * (CC/4);     // 16,777,216 float4
    film_kernel<<<n4/256, 256>>>((const float4*)x, (float4*)d_out);
}